// round 8
// baseline (speedup 1.0000x reference)
#include <cuda_runtime.h>

#define N_NODES 100000
#define E_EDGES 1600000
#define IN_C    128
#define H_C     64
#define OUT_C   32

// ---------------- scratch (no allocation allowed) ----------------
// NOTE: device symbols are ONLY referenced from device code (never passed as
// kernel arguments from host — host-side shadow address is not the device
// address, and on GB300/ATS it silently dereferences host memory).
__device__ __align__(16) float g_deg [N_NODES];
__device__ __align__(16) float g_dinv[N_NODES];
__device__ __align__(16) float g_t1  [N_NODES * H_C];  // x @ W1 (pre-aggregation)
__device__ __align__(16) float g_agg1[N_NODES * H_C];  // layer-1 aggregated (+b1)
__device__ __align__(16) float g_t2  [N_NODES * H_C];  // h @ [W_mu | W_logstd]
__device__ __align__(16) float g_agg2[N_NODES * H_C];  // layer-2 aggregated (+b2) = [mu | logstd]

// ---------------- degree / dinv ----------------
__global__ void k_zero_deg() {
    int n = blockIdx.x * blockDim.x + threadIdx.x;
    if (n < N_NODES) g_deg[n] = 0.0f;
}

__global__ void k_count_deg(const int* __restrict__ ei) {
    int e = blockIdx.x * blockDim.x + threadIdx.x;
    if (e < E_EDGES) atomicAdd(&g_deg[ei[E_EDGES + e]], 1.0f);
}

__global__ void k_dinv() {
    int n = blockIdx.x * blockDim.x + threadIdx.x;
    if (n < N_NODES) g_dinv[n] = rsqrtf(g_deg[n] + 1.0f);
}

// ---------------- matmul 1: t1 = x @ W1 ; agg1 = t1*dinv^2 + b1 ----------------
__global__ __launch_bounds__(256) void k_mm1(const float* __restrict__ x,
                                             const float* __restrict__ W1,
                                             const float* __restrict__ b1) {
    __shared__ float Ws[IN_C * H_C];   // 32 KB
    for (int i = threadIdx.x; i < IN_C * H_C; i += blockDim.x) Ws[i] = W1[i];
    __syncthreads();

    int n = blockIdx.x * blockDim.x + threadIdx.x;
    if (n >= N_NODES) return;

    float acc[H_C];
#pragma unroll
    for (int j = 0; j < H_C; j++) acc[j] = 0.0f;

    const float* xrow = x + (size_t)n * IN_C;
    for (int k4 = 0; k4 < IN_C / 4; k4++) {
        float4 xv = *(const float4*)(xrow + 4 * k4);
        float xk[4] = {xv.x, xv.y, xv.z, xv.w};
#pragma unroll
        for (int kk = 0; kk < 4; kk++) {
            const float4* wrow = (const float4*)(&Ws[(k4 * 4 + kk) * H_C]);
            float xs = xk[kk];
#pragma unroll
            for (int j = 0; j < H_C / 4; j++) {
                float4 w = wrow[j];
                acc[4 * j + 0] += xs * w.x;
                acc[4 * j + 1] += xs * w.y;
                acc[4 * j + 2] += xs * w.z;
                acc[4 * j + 3] += xs * w.w;
            }
        }
    }

    float di = g_dinv[n];
    float d2 = di * di;
    float4* t1 = (float4*)(g_t1   + (size_t)n * H_C);
    float4* a1 = (float4*)(g_agg1 + (size_t)n * H_C);
#pragma unroll
    for (int j = 0; j < H_C / 4; j++) {
        float4 t = make_float4(acc[4*j], acc[4*j+1], acc[4*j+2], acc[4*j+3]);
        t1[j] = t;
        float4 bb = *(const float4*)(b1 + 4 * j);
        a1[j] = make_float4(t.x * d2 + bb.x, t.y * d2 + bb.y,
                            t.z * d2 + bb.z, t.w * d2 + bb.w);
    }
}

// ---------------- edge aggregation: agg[dst] += dinv[s]*dinv[d] * t[src] ----------------
// layer 0: t = g_t1, agg = g_agg1    layer 1: t = g_t2, agg = g_agg2
__global__ __launch_bounds__(256) void k_edge(const int* __restrict__ ei, int layer) {
    long tid = (long)blockIdx.x * blockDim.x + threadIdx.x;
    if (tid >= (long)E_EDGES * (H_C / 4)) return;
    int e = (int)(tid >> 4);        // H_C/4 == 16 groups per edge
    int c = ((int)tid & 15) << 2;   // channel offset

    const float* t  = (layer == 0) ? g_t1  : g_t2;
    float*      agg = (layer == 0) ? g_agg1 : g_agg2;

    int s = ei[e];
    int d = ei[E_EDGES + e];
    float nm = g_dinv[s] * g_dinv[d];

    float4 v = *(const float4*)(t + (size_t)s * H_C + c);
    v.x *= nm; v.y *= nm; v.z *= nm; v.w *= nm;

    float* p = agg + (size_t)d * H_C + c;
    asm volatile("red.global.add.v4.f32 [%0], {%1, %2, %3, %4};"
                 :: "l"(p), "f"(v.x), "f"(v.y), "f"(v.z), "f"(v.w)
                 : "memory");
}

// ---------------- matmul 2: t2 = relu(agg1) @ [W_mu|W_logstd] ; agg2 = t2*dinv^2 + b2 ----------------
__global__ __launch_bounds__(256) void k_mm2(const float* __restrict__ Wmu,
                                             const float* __restrict__ Wls,
                                             const float* __restrict__ bmu,
                                             const float* __restrict__ bls) {
    __shared__ float Ws[H_C * H_C];   // 16 KB, columns = [W_mu | W_logstd]
    __shared__ float bs[H_C];
    for (int i = threadIdx.x; i < H_C * H_C; i += blockDim.x) {
        int k = i >> 6;        // /64
        int j = i & 63;
        Ws[i] = (j < OUT_C) ? Wmu[k * OUT_C + j] : Wls[k * OUT_C + (j - OUT_C)];
    }
    if (threadIdx.x < H_C)
        bs[threadIdx.x] = (threadIdx.x < OUT_C) ? bmu[threadIdx.x]
                                                : bls[threadIdx.x - OUT_C];
    __syncthreads();

    int n = blockIdx.x * blockDim.x + threadIdx.x;
    if (n >= N_NODES) return;

    float acc[H_C];
#pragma unroll
    for (int j = 0; j < H_C; j++) acc[j] = 0.0f;

    const float* hrow = g_agg1 + (size_t)n * H_C;
    for (int k4 = 0; k4 < H_C / 4; k4++) {
        float4 hv = *(const float4*)(hrow + 4 * k4);
        float hk[4] = {fmaxf(hv.x, 0.0f), fmaxf(hv.y, 0.0f),
                       fmaxf(hv.z, 0.0f), fmaxf(hv.w, 0.0f)};
#pragma unroll
        for (int kk = 0; kk < 4; kk++) {
            const float4* wrow = (const float4*)(&Ws[(k4 * 4 + kk) * H_C]);
            float hs = hk[kk];
#pragma unroll
            for (int j = 0; j < H_C / 4; j++) {
                float4 w = wrow[j];
                acc[4 * j + 0] += hs * w.x;
                acc[4 * j + 1] += hs * w.y;
                acc[4 * j + 2] += hs * w.z;
                acc[4 * j + 3] += hs * w.w;
            }
        }
    }

    float di = g_dinv[n];
    float d2 = di * di;
    float4* t2 = (float4*)(g_t2   + (size_t)n * H_C);
    float4* a2 = (float4*)(g_agg2 + (size_t)n * H_C);
#pragma unroll
    for (int j = 0; j < H_C / 4; j++) {
        float4 t = make_float4(acc[4*j], acc[4*j+1], acc[4*j+2], acc[4*j+3]);
        t2[j] = t;
        a2[j] = make_float4(t.x * d2 + bs[4*j+0], t.y * d2 + bs[4*j+1],
                            t.z * d2 + bs[4*j+2], t.w * d2 + bs[4*j+3]);
    }
}

// ---------------- write out: out = [mu (N*32) ; logstd (N*32)] ----------------
__global__ void k_writeout(float* __restrict__ out) {
    int tid = blockIdx.x * blockDim.x + threadIdx.x;   // N * 8 threads, float4 each
    if (tid >= N_NODES * (OUT_C / 4)) return;
    int n = tid >> 3;
    int q = (tid & 7) << 2;   // 0..28
    const float4* a = (const float4*)(g_agg2 + (size_t)n * H_C);
    float4 mu = a[q >> 2];
    float4 ls = a[(q + OUT_C) >> 2];
    *(float4*)(out + (size_t)n * OUT_C + q)                           = mu;
    *(float4*)(out + (size_t)N_NODES * OUT_C + (size_t)n * OUT_C + q) = ls;
}

// ---------------- launch ----------------
extern "C" void kernel_launch(void* const* d_in, const int* in_sizes, int n_in,
                              void* d_out, int out_size) {
    const float* x   = (const float*)d_in[0];
    const int*   ei  = (const int*)  d_in[1];
    const float* W1  = (const float*)d_in[2];
    const float* b1  = (const float*)d_in[3];
    const float* Wmu = (const float*)d_in[4];
    const float* bmu = (const float*)d_in[5];
    const float* Wls = (const float*)d_in[6];
    const float* bls = (const float*)d_in[7];
    float* out = (float*)d_out;

    const int TB = 256;
    k_zero_deg <<<(N_NODES + TB - 1) / TB, TB>>>();
    k_count_deg<<<(E_EDGES + TB - 1) / TB, TB>>>(ei);
    k_dinv     <<<(N_NODES + TB - 1) / TB, TB>>>();

    k_mm1<<<(N_NODES + TB - 1) / TB, TB>>>(x, W1, b1);

    long ethreads = (long)E_EDGES * (H_C / 4);
    int  eblocks  = (int)((ethreads + TB - 1) / TB);
    k_edge<<<eblocks, TB>>>(ei, 0);

    k_mm2<<<(N_NODES + TB - 1) / TB, TB>>>(Wmu, Wls, bmu, bls);

    k_edge<<<eblocks, TB>>>(ei, 1);

    int wthreads = N_NODES * (OUT_C / 4);
    k_writeout<<<(wthreads + TB - 1) / TB, TB>>>(out);
}

// round 13
// speedup vs baseline: 1.1457x; 1.1457x over previous
#include <cuda_runtime.h>

#define N_NODES 100000
#define E_EDGES 1600000
#define IN_C    128
#define H_C     64
#define OUT_C   32
#define NBLK    391          // ceil(N_NODES/256)

// ---------------- scratch (device-side access only!) ----------------
__device__ __align__(16) float g_dinv[N_NODES];
__device__ int   g_degi   [N_NODES];
__device__ int   g_cursor [N_NODES];
__device__ int   g_scani  [N_NODES];
__device__ int   g_rowstart[N_NODES];
__device__ int   g_bsum   [NBLK];
__device__ int   g_bpre   [512];
__device__ int   g_csr_src[E_EDGES];
__device__ __align__(16) float g_t1  [N_NODES * H_C];
__device__ __align__(16) float g_agg1[N_NODES * H_C];
__device__ __align__(16) float g_t2  [N_NODES * H_C];
__device__ __align__(16) float g_agg2[N_NODES * H_C];

// ---------------- degree / dinv / CSR build ----------------
__global__ void k_init() {
    int n = blockIdx.x * blockDim.x + threadIdx.x;
    if (n < N_NODES) { g_degi[n] = 0; g_cursor[n] = 0; }
}

__global__ void k_degcnt(const int* __restrict__ ei) {
    int e = blockIdx.x * blockDim.x + threadIdx.x;
    if (e < E_EDGES) atomicAdd(&g_degi[ei[E_EDGES + e]], 1);
}

__global__ void k_dinv() {
    int n = blockIdx.x * blockDim.x + threadIdx.x;
    if (n < N_NODES) g_dinv[n] = rsqrtf((float)g_degi[n] + 1.0f);
}

// block-local inclusive scan of degrees (256/block)
__global__ void k_scan_block() {
    __shared__ int sh[256];
    int tid = threadIdx.x;
    int i = blockIdx.x * 256 + tid;
    int v = (i < N_NODES) ? g_degi[i] : 0;
    sh[tid] = v;
    __syncthreads();
#pragma unroll
    for (int off = 1; off < 256; off <<= 1) {
        int t = (tid >= off) ? sh[tid - off] : 0;
        __syncthreads();
        sh[tid] += t;
        __syncthreads();
    }
    if (i < N_NODES) g_scani[i] = sh[tid];
    if (tid == 255) g_bsum[blockIdx.x] = sh[255];
}

// scan of block sums (one block, 512 threads; NBLK=391 < 512)
__global__ void k_scan_top() {
    __shared__ int sh[512];
    int tid = threadIdx.x;
    sh[tid] = (tid < NBLK) ? g_bsum[tid] : 0;
    __syncthreads();
#pragma unroll
    for (int off = 1; off < 512; off <<= 1) {
        int t = (tid >= off) ? sh[tid - off] : 0;
        __syncthreads();
        sh[tid] += t;
        __syncthreads();
    }
    g_bpre[tid] = sh[tid];   // inclusive block prefix
}

__global__ void k_scan_add() {
    int i = blockIdx.x * 256 + threadIdx.x;
    if (i < N_NODES) {
        int binc = (blockIdx.x > 0) ? g_bpre[blockIdx.x - 1] : 0;
        g_rowstart[i] = g_scani[i] - g_degi[i] + binc;   // exclusive prefix
    }
}

__global__ void k_fill(const int* __restrict__ ei) {
    int e = blockIdx.x * blockDim.x + threadIdx.x;
    if (e < E_EDGES) {
        int s = ei[e];
        int d = ei[E_EDGES + e];
        int pos = g_rowstart[d] + atomicAdd(&g_cursor[d], 1);
        g_csr_src[pos] = s;
    }
}

// ---------------- matmul 1: t1 = x @ W1  (4 nodes x 16 ch per thread) ----------------
__global__ __launch_bounds__(256) void k_mm1(const float* __restrict__ x,
                                             const float* __restrict__ W1) {
    __shared__ float Ws[IN_C * H_C];   // 32 KB
    for (int i = threadIdx.x; i < IN_C * H_C; i += 256) Ws[i] = W1[i];
    __syncthreads();

    int tid  = threadIdx.x;
    int quad = blockIdx.x * 64 + (tid >> 2);   // 64 quads/block, 4 nodes each
    int nb   = quad * 4;
    if (nb >= N_NODES) return;
    int cb = (tid & 3) << 4;                   // 16-channel group

    float acc[4][16];
#pragma unroll
    for (int j = 0; j < 4; j++)
#pragma unroll
        for (int c = 0; c < 16; c++) acc[j][c] = 0.0f;

    const float* xb = x + (size_t)nb * IN_C;
    for (int k4 = 0; k4 < IN_C / 4; k4++) {
        float4 xv[4];
#pragma unroll
        for (int j = 0; j < 4; j++)
            xv[j] = (nb + j < N_NODES)
                  ? *(const float4*)(xb + (size_t)j * IN_C + k4 * 4)
                  : make_float4(0.f, 0.f, 0.f, 0.f);
#pragma unroll
        for (int kk = 0; kk < 4; kk++) {
            const float4* wr = (const float4*)(&Ws[(k4 * 4 + kk) * H_C + cb]);
            float4 w0 = wr[0], w1 = wr[1], w2 = wr[2], w3 = wr[3];
#pragma unroll
            for (int j = 0; j < 4; j++) {
                float xs = (kk == 0) ? xv[j].x : (kk == 1) ? xv[j].y
                         : (kk == 2) ? xv[j].z : xv[j].w;
                acc[j][0]  += xs * w0.x; acc[j][1]  += xs * w0.y;
                acc[j][2]  += xs * w0.z; acc[j][3]  += xs * w0.w;
                acc[j][4]  += xs * w1.x; acc[j][5]  += xs * w1.y;
                acc[j][6]  += xs * w1.z; acc[j][7]  += xs * w1.w;
                acc[j][8]  += xs * w2.x; acc[j][9]  += xs * w2.y;
                acc[j][10] += xs * w2.z; acc[j][11] += xs * w2.w;
                acc[j][12] += xs * w3.x; acc[j][13] += xs * w3.y;
                acc[j][14] += xs * w3.z; acc[j][15] += xs * w3.w;
            }
        }
    }

#pragma unroll
    for (int j = 0; j < 4; j++) {
        if (nb + j < N_NODES) {
            float4* o = (float4*)(g_t1 + (size_t)(nb + j) * H_C + cb);
#pragma unroll
            for (int q = 0; q < 4; q++)
                o[q] = make_float4(acc[j][4*q], acc[j][4*q+1],
                                   acc[j][4*q+2], acc[j][4*q+3]);
        }
    }
}

// ---------------- gather: agg[n] = dinv[n]*sum_s dinv[s]*t[s] + t[n]*dinv[n]^2 + bias ----
// warp per dst node; 2 channels per lane; 2-edge software pipeline
__global__ __launch_bounds__(256) void k_gather(int layer,
                                                const float* __restrict__ bA,
                                                const float* __restrict__ bB) {
    int gw = (blockIdx.x * 256 + threadIdx.x) >> 5;   // global warp = node
    int lane = threadIdx.x & 31;
    if (gw >= N_NODES) return;
    int n = gw;

    const float* t  = layer ? g_t2  : g_t1;
    float*      agg = layer ? g_agg2 : g_agg1;

    int rs = g_rowstart[n];
    int dg = g_degi[n];
    float dd = g_dinv[n];
    int c = lane * 2;

    float a0 = 0.f, a1 = 0.f, p0 = 0.f, p1 = 0.f;
    int i = 0;
    for (; i + 2 <= dg; i += 2) {
        int s0 = g_csr_src[rs + i];
        int s1 = g_csr_src[rs + i + 1];
        float ds0 = g_dinv[s0];
        float ds1 = g_dinv[s1];
        float2 v0 = *(const float2*)(t + (size_t)s0 * H_C + c);
        float2 v1 = *(const float2*)(t + (size_t)s1 * H_C + c);
        a0 += ds0 * v0.x; a1 += ds0 * v0.y;
        p0 += ds1 * v1.x; p1 += ds1 * v1.y;
    }
    if (i < dg) {
        int s = g_csr_src[rs + i];
        float ds = g_dinv[s];
        float2 v = *(const float2*)(t + (size_t)s * H_C + c);
        a0 += ds * v.x; a1 += ds * v.y;
    }
    a0 = (a0 + p0) * dd;
    a1 = (a1 + p1) * dd;

    float2 self = *(const float2*)(t + (size_t)n * H_C + c);
    float bias0 = (c < 32) ? bA[c]     : bB[c - 32];
    float bias1 = (c < 32) ? bA[c + 1] : bB[c + 1 - 32];
    a0 += self.x * dd * dd + bias0;
    a1 += self.y * dd * dd + bias1;

    *(float2*)(agg + (size_t)n * H_C + c) = make_float2(a0, a1);
}

// ---------------- matmul 2: t2 = relu(agg1) @ [W_mu|W_logstd] ----------------
__global__ __launch_bounds__(256) void k_mm2(const float* __restrict__ Wmu,
                                             const float* __restrict__ Wls) {
    __shared__ float Ws[H_C * H_C];   // 16 KB, columns = [W_mu | W_logstd]
    for (int i = threadIdx.x; i < H_C * H_C; i += 256) {
        int k = i >> 6;
        int j = i & 63;
        Ws[i] = (j < OUT_C) ? Wmu[k * OUT_C + j] : Wls[k * OUT_C + (j - OUT_C)];
    }
    __syncthreads();

    int tid  = threadIdx.x;
    int quad = blockIdx.x * 64 + (tid >> 2);
    int nb   = quad * 4;
    if (nb >= N_NODES) return;
    int cb = (tid & 3) << 4;

    float acc[4][16];
#pragma unroll
    for (int j = 0; j < 4; j++)
#pragma unroll
        for (int c = 0; c < 16; c++) acc[j][c] = 0.0f;

    const float* hb = g_agg1 + (size_t)nb * H_C;
    for (int k4 = 0; k4 < H_C / 4; k4++) {
        float4 xv[4];
#pragma unroll
        for (int j = 0; j < 4; j++) {
            if (nb + j < N_NODES) {
                float4 h = *(const float4*)(hb + (size_t)j * H_C + k4 * 4);
                xv[j] = make_float4(fmaxf(h.x, 0.f), fmaxf(h.y, 0.f),
                                    fmaxf(h.z, 0.f), fmaxf(h.w, 0.f));
            } else xv[j] = make_float4(0.f, 0.f, 0.f, 0.f);
        }
#pragma unroll
        for (int kk = 0; kk < 4; kk++) {
            const float4* wr = (const float4*)(&Ws[(k4 * 4 + kk) * H_C + cb]);
            float4 w0 = wr[0], w1 = wr[1], w2 = wr[2], w3 = wr[3];
#pragma unroll
            for (int j = 0; j < 4; j++) {
                float xs = (kk == 0) ? xv[j].x : (kk == 1) ? xv[j].y
                         : (kk == 2) ? xv[j].z : xv[j].w;
                acc[j][0]  += xs * w0.x; acc[j][1]  += xs * w0.y;
                acc[j][2]  += xs * w0.z; acc[j][3]  += xs * w0.w;
                acc[j][4]  += xs * w1.x; acc[j][5]  += xs * w1.y;
                acc[j][6]  += xs * w1.z; acc[j][7]  += xs * w1.w;
                acc[j][8]  += xs * w2.x; acc[j][9]  += xs * w2.y;
                acc[j][10] += xs * w2.z; acc[j][11] += xs * w2.w;
                acc[j][12] += xs * w3.x; acc[j][13] += xs * w3.y;
                acc[j][14] += xs * w3.z; acc[j][15] += xs * w3.w;
            }
        }
    }

#pragma unroll
    for (int j = 0; j < 4; j++) {
        if (nb + j < N_NODES) {
            float4* o = (float4*)(g_t2 + (size_t)(nb + j) * H_C + cb);
#pragma unroll
            for (int q = 0; q < 4; q++)
                o[q] = make_float4(acc[j][4*q], acc[j][4*q+1],
                                   acc[j][4*q+2], acc[j][4*q+3]);
        }
    }
}

// ---------------- write out: out = [mu (N*32) ; logstd (N*32)] ----------------
__global__ void k_writeout(float* __restrict__ out) {
    int tid = blockIdx.x * blockDim.x + threadIdx.x;   // N * 8 threads, float4 each
    if (tid >= N_NODES * (OUT_C / 4)) return;
    int n = tid >> 3;
    int q = (tid & 7) << 2;
    const float4* a = (const float4*)(g_agg2 + (size_t)n * H_C);
    float4 mu = a[q >> 2];
    float4 ls = a[(q + OUT_C) >> 2];
    *(float4*)(out + (size_t)n * OUT_C + q)                           = mu;
    *(float4*)(out + (size_t)N_NODES * OUT_C + (size_t)n * OUT_C + q) = ls;
}

// ---------------- launch ----------------
extern "C" void kernel_launch(void* const* d_in, const int* in_sizes, int n_in,
                              void* d_out, int out_size) {
    const float* x   = (const float*)d_in[0];
    const int*   ei  = (const int*)  d_in[1];
    const float* W1  = (const float*)d_in[2];
    const float* b1  = (const float*)d_in[3];
    const float* Wmu = (const float*)d_in[4];
    const float* bmu = (const float*)d_in[5];
    const float* Wls = (const float*)d_in[6];
    const float* bls = (const float*)d_in[7];
    float* out = (float*)d_out;

    const int TB = 256;
    const int EB = (E_EDGES + TB - 1) / TB;   // 6250

    k_init      <<<NBLK, TB>>>();
    k_degcnt    <<<EB,   TB>>>(ei);
    k_dinv      <<<NBLK, TB>>>();
    k_scan_block<<<NBLK, TB>>>();
    k_scan_top  <<<1,   512>>>();
    k_scan_add  <<<NBLK, TB>>>();
    k_fill      <<<EB,   TB>>>(ei);

    k_mm1<<<NBLK, TB>>>(x, W1);                       // 256 nodes/block

    int gblocks = (N_NODES * 32 + TB - 1) / TB;        // warp per node = 12500
    k_gather<<<gblocks, TB>>>(0, b1, b1 + 32);

    k_mm2<<<NBLK, TB>>>(Wmu, Wls);

    k_gather<<<gblocks, TB>>>(1, bmu, bls);

    int wthreads = N_NODES * (OUT_C / 4);
    k_writeout<<<(wthreads + TB - 1) / TB, TB>>>(out);
}

// round 14
// speedup vs baseline: 1.3366x; 1.1667x over previous
#include <cuda_runtime.h>

#define N_NODES 100000
#define E_EDGES 1600000
#define IN_C    128
#define H_C     64
#define OUT_C   32
#define NBLK    391          // ceil(N_NODES/256)

// ---------------- scratch (device-side access only!) ----------------
__device__ __align__(16) float g_dinv[N_NODES];
__device__ int   g_degi    [N_NODES];
__device__ int   g_cursor  [N_NODES];
__device__ int   g_scani   [N_NODES];
__device__ int   g_rowstart[N_NODES];
__device__ int   g_bsum    [NBLK];
__device__ int   g_bpre    [512];
__device__ int   g_csr_src [E_EDGES];
__device__ __align__(16) float g_t1  [N_NODES * H_C];
__device__ __align__(16) float g_agg1[N_NODES * H_C];   // relu already applied
__device__ __align__(16) float g_t2  [N_NODES * H_C];

// ---------------- packed f32x2 helpers ----------------
__device__ __forceinline__ unsigned long long pack2(float x) {
    unsigned long long r;
    asm("mov.b64 %0, {%1, %1};" : "=l"(r) : "f"(x));
    return r;
}
__device__ __forceinline__ void fma2(unsigned long long& d,
                                     unsigned long long a,
                                     unsigned long long b) {
    asm("fma.rn.f32x2 %0, %1, %2, %0;" : "+l"(d) : "l"(a), "l"(b));
}

// ---------------- degree / CSR build ----------------
__global__ void k_init() {
    int n = blockIdx.x * blockDim.x + threadIdx.x;
    if (n < N_NODES) { g_degi[n] = 0; g_cursor[n] = 0; }
}

__global__ void k_degcnt(const int* __restrict__ ei) {
    int e = blockIdx.x * blockDim.x + threadIdx.x;
    if (e < E_EDGES) atomicAdd(&g_degi[ei[E_EDGES + e]], 1);
}

// block-local inclusive scan of degrees (256/block)
__global__ void k_scan_block() {
    __shared__ int sh[256];
    int tid = threadIdx.x;
    int i = blockIdx.x * 256 + tid;
    int v = (i < N_NODES) ? g_degi[i] : 0;
    sh[tid] = v;
    __syncthreads();
#pragma unroll
    for (int off = 1; off < 256; off <<= 1) {
        int t = (tid >= off) ? sh[tid - off] : 0;
        __syncthreads();
        sh[tid] += t;
        __syncthreads();
    }
    if (i < N_NODES) g_scani[i] = sh[tid];
    if (tid == 255) g_bsum[blockIdx.x] = sh[255];
}

// scan of block sums (one block, 512 threads; NBLK=391 < 512)
__global__ void k_scan_top() {
    __shared__ int sh[512];
    int tid = threadIdx.x;
    sh[tid] = (tid < NBLK) ? g_bsum[tid] : 0;
    __syncthreads();
#pragma unroll
    for (int off = 1; off < 512; off <<= 1) {
        int t = (tid >= off) ? sh[tid - off] : 0;
        __syncthreads();
        sh[tid] += t;
        __syncthreads();
    }
    g_bpre[tid] = sh[tid];   // inclusive block prefix
}

// exclusive prefix -> rowstart; also compute dinv here (fused)
__global__ void k_scan_add() {
    int i = blockIdx.x * 256 + threadIdx.x;
    if (i < N_NODES) {
        int binc = (blockIdx.x > 0) ? g_bpre[blockIdx.x - 1] : 0;
        int dg = g_degi[i];
        g_rowstart[i] = g_scani[i] - dg + binc;
        g_dinv[i] = rsqrtf((float)dg + 1.0f);
    }
}

__global__ void k_fill(const int* __restrict__ ei) {
    int e = blockIdx.x * blockDim.x + threadIdx.x;
    if (e < E_EDGES) {
        int s = ei[e];
        int d = ei[E_EDGES + e];
        int pos = g_rowstart[d] + atomicAdd(&g_cursor[d], 1);
        g_csr_src[pos] = s;
    }
}

// ---------------- matmul 1: t1 = x @ W1  (4 nodes x 16 ch per thread, f32x2) ----------
__global__ __launch_bounds__(256) void k_mm1(const float* __restrict__ x,
                                             const float* __restrict__ W1) {
    __shared__ float Ws[IN_C * H_C];   // 32 KB
    for (int i = threadIdx.x; i < IN_C * H_C; i += 256) Ws[i] = W1[i];
    __syncthreads();

    int tid  = threadIdx.x;
    int quad = blockIdx.x * 64 + (tid >> 2);
    int nb   = quad * 4;
    if (nb >= N_NODES) return;
    int cb = (tid & 3) << 4;   // 16-channel group

    unsigned long long acc[4][8];
#pragma unroll
    for (int j = 0; j < 4; j++)
#pragma unroll
        for (int q = 0; q < 8; q++) acc[j][q] = 0ull;

    const float* xb = x + (size_t)nb * IN_C;
    for (int k4 = 0; k4 < IN_C / 4; k4++) {
        float4 xv[4];
#pragma unroll
        for (int j = 0; j < 4; j++)
            xv[j] = (nb + j < N_NODES)
                  ? *(const float4*)(xb + (size_t)j * IN_C + k4 * 4)
                  : make_float4(0.f, 0.f, 0.f, 0.f);
#pragma unroll
        for (int kk = 0; kk < 4; kk++) {
            const ulonglong2* wr = (const ulonglong2*)(&Ws[(k4 * 4 + kk) * H_C + cb]);
            ulonglong2 wv0 = wr[0], wv1 = wr[1], wv2 = wr[2], wv3 = wr[3];
            unsigned long long w[8] = {wv0.x, wv0.y, wv1.x, wv1.y,
                                       wv2.x, wv2.y, wv3.x, wv3.y};
#pragma unroll
            for (int j = 0; j < 4; j++) {
                float xs = (kk == 0) ? xv[j].x : (kk == 1) ? xv[j].y
                         : (kk == 2) ? xv[j].z : xv[j].w;
                unsigned long long xp = pack2(xs);
#pragma unroll
                for (int q = 0; q < 8; q++) fma2(acc[j][q], xp, w[q]);
            }
        }
    }

#pragma unroll
    for (int j = 0; j < 4; j++) {
        if (nb + j < N_NODES) {
            ulonglong2* o = (ulonglong2*)(g_t1 + (size_t)(nb + j) * H_C + cb);
#pragma unroll
            for (int q = 0; q < 4; q++) {
                ulonglong2 v; v.x = acc[j][2*q]; v.y = acc[j][2*q+1];
                o[q] = v;
            }
        }
    }
}

// ---------------- gather ----------------
// agg[n] = dinv[n]*sum_s dinv[s]*t[s] + t[n]*dinv[n]^2 + bias
// layer 0: t = g_t1, write relu(result) to g_agg1
// layer 1: t = g_t2, write split [mu ; logstd] directly to out
// warp per dst node; 2 channels per lane; 4-edge software pipeline
__global__ __launch_bounds__(256) void k_gather(int layer,
                                                const float* __restrict__ bA,
                                                const float* __restrict__ bB,
                                                float* __restrict__ outp) {
    int gw = (blockIdx.x * 256 + threadIdx.x) >> 5;
    int lane = threadIdx.x & 31;
    if (gw >= N_NODES) return;
    int n = gw;

    const float* t = layer ? g_t2 : g_t1;

    int rs = g_rowstart[n];
    int dg = g_degi[n];
    float dd = g_dinv[n];
    int c = lane * 2;

    float a0 = 0.f, a1 = 0.f, b0 = 0.f, b1 = 0.f;
    float c0 = 0.f, c1 = 0.f, d0 = 0.f, d1 = 0.f;
    int i = 0;
    for (; i + 4 <= dg; i += 4) {
        int s0 = g_csr_src[rs + i];
        int s1 = g_csr_src[rs + i + 1];
        int s2 = g_csr_src[rs + i + 2];
        int s3 = g_csr_src[rs + i + 3];
        float e0 = g_dinv[s0], e1 = g_dinv[s1];
        float e2 = g_dinv[s2], e3 = g_dinv[s3];
        float2 v0 = *(const float2*)(t + (size_t)s0 * H_C + c);
        float2 v1 = *(const float2*)(t + (size_t)s1 * H_C + c);
        float2 v2 = *(const float2*)(t + (size_t)s2 * H_C + c);
        float2 v3 = *(const float2*)(t + (size_t)s3 * H_C + c);
        a0 += e0 * v0.x; a1 += e0 * v0.y;
        b0 += e1 * v1.x; b1 += e1 * v1.y;
        c0 += e2 * v2.x; c1 += e2 * v2.y;
        d0 += e3 * v3.x; d1 += e3 * v3.y;
    }
    for (; i < dg; i++) {
        int s = g_csr_src[rs + i];
        float ds = g_dinv[s];
        float2 v = *(const float2*)(t + (size_t)s * H_C + c);
        a0 += ds * v.x; a1 += ds * v.y;
    }
    a0 = ((a0 + b0) + (c0 + d0)) * dd;
    a1 = ((a1 + b1) + (c1 + d1)) * dd;

    float2 self = *(const float2*)(t + (size_t)n * H_C + c);
    float bias0 = (c < 32) ? bA[c]     : bB[c - 32];
    float bias1 = (c < 32) ? bA[c + 1] : bB[c + 1 - 32];
    a0 += self.x * dd * dd + bias0;
    a1 += self.y * dd * dd + bias1;

    if (layer == 0) {
        // ReLU applied here; agg1 is only read by mm2
        *(float2*)(g_agg1 + (size_t)n * H_C + c) =
            make_float2(fmaxf(a0, 0.f), fmaxf(a1, 0.f));
    } else {
        // direct writeout: [mu (N*32) ; logstd (N*32)]
        size_t idx = (c < 32)
            ? (size_t)n * OUT_C + c
            : (size_t)N_NODES * OUT_C + (size_t)n * OUT_C + (c - 32);
        *(float2*)(outp + idx) = make_float2(a0, a1);
    }
}

// ---------------- matmul 2: t2 = agg1 @ [W_mu|W_logstd]  (agg1 already relu'd) --------
__global__ __launch_bounds__(256) void k_mm2(const float* __restrict__ Wmu,
                                             const float* __restrict__ Wls) {
    __shared__ float Ws[H_C * H_C];   // 16 KB, columns = [W_mu | W_logstd]
    for (int i = threadIdx.x; i < H_C * H_C; i += 256) {
        int k = i >> 6;
        int j = i & 63;
        Ws[i] = (j < OUT_C) ? Wmu[k * OUT_C + j] : Wls[k * OUT_C + (j - OUT_C)];
    }
    __syncthreads();

    int tid  = threadIdx.x;
    int quad = blockIdx.x * 64 + (tid >> 2);
    int nb   = quad * 4;
    if (nb >= N_NODES) return;
    int cb = (tid & 3) << 4;

    unsigned long long acc[4][8];
#pragma unroll
    for (int j = 0; j < 4; j++)
#pragma unroll
        for (int q = 0; q < 8; q++) acc[j][q] = 0ull;

    const float* hb = g_agg1 + (size_t)nb * H_C;
    for (int k4 = 0; k4 < H_C / 4; k4++) {
        float4 xv[4];
#pragma unroll
        for (int j = 0; j < 4; j++)
            xv[j] = (nb + j < N_NODES)
                  ? *(const float4*)(hb + (size_t)j * H_C + k4 * 4)
                  : make_float4(0.f, 0.f, 0.f, 0.f);
#pragma unroll
        for (int kk = 0; kk < 4; kk++) {
            const ulonglong2* wr = (const ulonglong2*)(&Ws[(k4 * 4 + kk) * H_C + cb]);
            ulonglong2 wv0 = wr[0], wv1 = wr[1], wv2 = wr[2], wv3 = wr[3];
            unsigned long long w[8] = {wv0.x, wv0.y, wv1.x, wv1.y,
                                       wv2.x, wv2.y, wv3.x, wv3.y};
#pragma unroll
            for (int j = 0; j < 4; j++) {
                float xs = (kk == 0) ? xv[j].x : (kk == 1) ? xv[j].y
                         : (kk == 2) ? xv[j].z : xv[j].w;
                unsigned long long xp = pack2(xs);
#pragma unroll
                for (int q = 0; q < 8; q++) fma2(acc[j][q], xp, w[q]);
            }
        }
    }

#pragma unroll
    for (int j = 0; j < 4; j++) {
        if (nb + j < N_NODES) {
            ulonglong2* o = (ulonglong2*)(g_t2 + (size_t)(nb + j) * H_C + cb);
#pragma unroll
            for (int q = 0; q < 4; q++) {
                ulonglong2 v; v.x = acc[j][2*q]; v.y = acc[j][2*q+1];
                o[q] = v;
            }
        }
    }
}

// ---------------- launch ----------------
extern "C" void kernel_launch(void* const* d_in, const int* in_sizes, int n_in,
                              void* d_out, int out_size) {
    const float* x   = (const float*)d_in[0];
    const int*   ei  = (const int*)  d_in[1];
    const float* W1  = (const float*)d_in[2];
    const float* b1  = (const float*)d_in[3];
    const float* Wmu = (const float*)d_in[4];
    const float* bmu = (const float*)d_in[5];
    const float* Wls = (const float*)d_in[6];
    const float* bls = (const float*)d_in[7];
    float* out = (float*)d_out;

    const int TB = 256;
    const int EB = (E_EDGES + TB - 1) / TB;   // 6250

    k_init      <<<NBLK, TB>>>();
    k_degcnt    <<<EB,   TB>>>(ei);
    k_scan_block<<<NBLK, TB>>>();
    k_scan_top  <<<1,   512>>>();
    k_scan_add  <<<NBLK, TB>>>();
    k_fill      <<<EB,   TB>>>(ei);

    k_mm1<<<NBLK, TB>>>(x, W1);

    int gblocks = (N_NODES * 32 + TB - 1) / TB;   // warp per node = 12500
    k_gather<<<gblocks, TB>>>(0, b1, b1 + 32, nullptr);

    k_mm2<<<NBLK, TB>>>(Wmu, Wls);

    k_gather<<<gblocks, TB>>>(1, bmu, bls, out);
}